// round 9
// baseline (speedup 1.0000x reference)
#include <cuda_runtime.h>

// sLSTM, T=512 serial steps, B=16, HID=1024, H=4 heads (D=256), G=4 gates.
// R8: partition = 4 heads x 4 batch-groups x 8 channel-groups = 128 CTAs.
// Batches are independent -> sync domain is only the 8 CTAs sharing
// (head, batch-group). Per CTA: 32 channels x 4 batches; GEMM 128 rows x 4 b
// x 256 k with W in registers (128/thread), f32x2 FMA, shfl k-reduction.
// Per-warp flag release; h exchanged through `out` (t-indexed, race-free).

#define T_STEPS 512
#define BATCH   16
#define HID     1024
#define NCTA    128
#define TPB     256
#define SRS     17     // sRaw channel stride (words): [ch*17 + gate*4 + bl]

__device__ unsigned g_flag[NCTA * 4];   // [cta*4 + warp] = steps completed

__global__ void prep_kernel() {
    int i = threadIdx.x;
    if (i < NCTA * 4) g_flag[i] = 0u;
}

__device__ __forceinline__ void ffma2(unsigned long long &acc,
                                      unsigned long long a,
                                      unsigned long long b) {
    asm("fma.rn.f32x2 %0, %1, %2, %0;" : "+l"(acc) : "l"(a), "l"(b));
}
__device__ __forceinline__ float fold2(unsigned long long a) {
    return __uint_as_float((unsigned)(a & 0xffffffffu)) +
           __uint_as_float((unsigned)(a >> 32));
}
__device__ __forceinline__ float logsigf(float v) {
    float l = log1pf(expf(-fabsf(v)));
    return (v < 0.0f ? v : 0.0f) - l;
}
__device__ __forceinline__ unsigned ld_acq(const unsigned* p) {
    unsigned v;
    asm volatile("ld.acquire.gpu.global.u32 %0, [%1];" : "=r"(v) : "l"(p));
    return v;
}
__device__ __forceinline__ void st_rel(unsigned* p, unsigned v) {
    asm volatile("st.release.gpu.global.u32 [%0], %1;" :: "l"(p), "r"(v) : "memory");
}

__global__ __launch_bounds__(TPB, 1) void slstm_kernel(
    const float* __restrict__ x,     // (512, 16, 4096)
    const float* __restrict__ rk,    // (4, 256, 4, 256)
    const float* __restrict__ bias,  // flat 4096 (gate-major layout at raw pos)
    float* __restrict__ out)         // outs (512,16,1024) ++ final (4,16,1024)
{
    // h tile: 4 batch rows x 64 float4 (k=256), stride 65 f4, XOR-swizzled
    __shared__ float4 sH4[4 * 65];
    __shared__ float  sRaw[32 * SRS + 4];

    const int c     = blockIdx.x;
    const int head  = c >> 5;          // 4
    const int bg    = (c >> 3) & 3;    // 4 batch groups
    const int cg    = c & 7;           // 8 channel groups
    const int dd0   = cg << 5;         // 32 channels
    const int b0    = bg << 2;         // 4 batches
    const int hbase = head << 8;
    const int tid   = threadIdx.x;
    const int wq    = tid >> 5;        // warp: channels 4wq..4wq+3, all 4 gates
    const int lane  = tid & 31;
    const int rq    = lane & 3;        // channel within warp
    const int ks    = lane >> 2;       // k-slice: d in [32ks, 32ks+32)
    const int ch_t  = (wq << 2) + rq;  // this thread's channel (0..31)

    // ---- one-time W gather into registers ----
    // W[gate i][d] for channel dd = dd0+ch_t:
    //   rk[head, (d%64)*4 + i, dd/64, (dd%64)*4 + d/64]
    float Wf[128];   // [(i*8 + j)*4 + e], d = 32ks + 4j + e
    {
        const int dd  = dd0 + ch_t;
        const int gx  = dd >> 6;
        const int bbs = (dd & 63) << 2;
        #pragma unroll
        for (int i = 0; i < 4; ++i) {
            #pragma unroll
            for (int j = 0; j < 8; ++j) {
                #pragma unroll
                for (int e = 0; e < 4; ++e) {
                    int d  = 32 * ks + 4 * j + e;
                    int a  = ((d & 63) << 2) + i;
                    int bb = bbs + (d >> 6);
                    Wf[(i * 8 + j) * 4 + e] =
                        __ldg(&rk[((hbase + a) * 4 + gx) * 256 + bb]);
                }
            }
        }
    }
    const unsigned long long* W2 = (const unsigned long long*)Wf;

    // ---- elementwise role: tid<128 owns (channel ch_u, batch b0+bl_u) ----
    const int ch_u = tid >> 2;         // 0..31
    const int bl_u = tid & 3;          // 0..3
    const int q_u  = hbase + dd0 + ch_u;
    float bias_g[4];
    #pragma unroll
    for (int g = 0; g < 4; ++g)
        bias_g[g] = bias[(g << 10) + q_u];
    float st_h = 0.f, st_c = 0.f, st_n = 0.f, st_m = 0.f;

    // h_{-1} = 0
    if (tid < 4 * 65) sH4[tid] = make_float4(0.f, 0.f, 0.f, 0.f);
    __syncthreads();

    const unsigned long long* sH2 = (const unsigned long long*)sH4;
    // flag block for this (head, bg): 8 sibling CTAs x 4 warps = 32 flags
    const unsigned* fl = &g_flag[((head << 5) + (bg << 3)) << 2];

    for (int t = 0; t < T_STEPS; ++t) {
        // x prefetch (independent of h) — before the poll
        float xr0 = 0.f, xr1 = 0.f, xr2 = 0.f, xr3 = 0.f;
        if (tid < 128) {
            const float* xb = x + (size_t)(t * BATCH + b0 + bl_u) * 4096 + q_u;
            xr0 = __ldg(xb);
            xr1 = __ldg(xb + 1024);
            xr2 = __ldg(xb + 2048);
            xr3 = __ldg(xb + 3072);
        }

        if (t > 0) {
            if (wq == 0) {   // warp 0 polls all 32 producer-warp flags
                const unsigned tgt = (unsigned)t;
                for (;;) {
                    unsigned f = ld_acq(&fl[lane]);
                    if (__all_sync(0xffffffffu, f >= tgt)) break;
                }
            }
            __syncthreads();
            // stage h_{t-1}: 4 batches x 256 ch = 256 float4, 1 per thread
            {
                const float4* hsrc = (const float4*)(out +
                    (size_t)(t - 1) * (BATCH * HID) + (size_t)b0 * HID + hbase);
                int bl = tid >> 6;
                int f  = tid & 63;
                int s  = bl * 65 + (f & 56) + ((f ^ (f >> 3)) & 7);
                sH4[s] = __ldcg(hsrc + (bl << 8) + f);
            }
            __syncthreads();
        }

        // ---- GEMM: 4 gates x 4 batches for channel ch_t, k-slice 32ks ----
        unsigned long long acc[16];
        #pragma unroll
        for (int q = 0; q < 16; ++q) acc[q] = 0ull;

        #pragma unroll
        for (int j = 0; j < 8; ++j) {
            // slot (j ^ ks) holds logical f4 element (8ks + j)
            unsigned long long hlo[4], hhi[4];
            #pragma unroll
            for (int bl = 0; bl < 4; ++bl) {
                int idx = (bl * 65 + (ks << 3) + ((j ^ ks) & 7)) << 1;
                hlo[bl] = sH2[idx];
                hhi[bl] = sH2[idx + 1];
            }
            #pragma unroll
            for (int i = 0; i < 4; ++i) {
                unsigned long long wlo = W2[(i * 8 + j) * 2];
                unsigned long long whi = W2[(i * 8 + j) * 2 + 1];
                #pragma unroll
                for (int bl = 0; bl < 4; ++bl) {
                    ffma2(acc[i * 4 + bl], wlo, hlo[bl]);
                    ffma2(acc[i * 4 + bl], whi, hhi[bl]);
                }
            }
        }

        // k-reduction across the 8 ks groups (lane stride 4)
        #pragma unroll
        for (int q = 0; q < 16; ++q) {
            float v = fold2(acc[q]);
            v += __shfl_xor_sync(0xffffffffu, v, 4);
            v += __shfl_xor_sync(0xffffffffu, v, 8);
            v += __shfl_xor_sync(0xffffffffu, v, 16);
            if (ks == 0) {
                int i  = q >> 2;       // gate
                int bl = q & 3;        // batch
                sRaw[ch_t * SRS + i * 4 + bl] = v;
            }
        }
        __syncthreads();

        // ---- elementwise state update; h_t straight into out ----
        if (tid < 128) {
            const float* rw = &sRaw[ch_u * SRS + bl_u];
            float iraw = rw[ 0] + xr0 + bias_g[0];
            float fraw = rw[ 4] + xr1 + bias_g[1];
            float zraw = rw[ 8] + xr2 + bias_g[2];
            float oraw = rw[12] + xr3 + bias_g[3];
            float lf   = st_m + logsigf(fraw);
            float mnew = (t == 0) ? iraw : fmaxf(iraw, lf);  // all(n==0) only at t=0
            float og   = 1.0f / (1.0f + expf(-oraw));
            float ig   = expf(iraw - mnew);
            float fg   = expf(lf - mnew);
            float cn   = fg * st_c + ig * tanhf(zraw);
            float nn   = fg * st_h + ig;                     // reference uses h here
            float hn   = og * cn / nn;
            st_c = cn; st_n = nn; st_m = mnew; st_h = hn;
            __stcg(&out[(size_t)(t * BATCH + b0 + bl_u) * HID + q_u], hn);
            __syncwarp();
            if (lane == 0) st_rel(&g_flag[(c << 2) + wq], (unsigned)(t + 1));
        }
        // no CTA barrier here: sRaw/sH rewrites for t+1 are fenced by the
        // post-poll __syncthreads; flags are monotonic per producer warp
    }

    if (tid < 128) {
        const size_t FS = (size_t)T_STEPS * BATCH * HID;
        const size_t o  = (size_t)(b0 + bl_u) * HID + q_u;
        out[FS + 0 * BATCH * HID + o] = st_h;
        out[FS + 1 * BATCH * HID + o] = st_c;
        out[FS + 2 * BATCH * HID + o] = st_n;
        out[FS + 3 * BATCH * HID + o] = st_m;
    }
}

extern "C" void kernel_launch(void* const* d_in, const int* in_sizes, int n_in,
                              void* d_out, int out_size) {
    const float* x    = (const float*)d_in[0];
    const float* rk   = (const float*)d_in[1];
    const float* bias = (const float*)d_in[2];
    float* out        = (float*)d_out;

    prep_kernel<<<1, NCTA * 4>>>();
    slstm_kernel<<<NCTA, TPB>>>(x, rk, bias, out);
}